// round 4
// baseline (speedup 1.0000x reference)
#include <cuda_runtime.h>

// Fused SSIM loss. pred/target: [32,1,512,512] f32, WIN=11 VALID -> 502x502.
// out[0] = 1 - mean(S).
//
// One kernel: per-band fused box filters (vertical sliding register sums,
// horizontal via swizzled smem with 8 cols/thread), SSIM, block partials,
// and a deterministic last-block final reduction (atomic ticket).
// R3: NBANDS 32->63 (RPB 8) to lift grid-limited occupancy (20% -> ~42%).

#define BATCH   32
#define HH      512
#define WW      512
#define WIN     11
#define OHH     502
#define OWW     502
#define NBANDS  63
#define RPB     8
#define TPB     64
#define NBLK    (BATCH * NBANDS)   // 2016

__device__ float        g_partial[NBLK];
__device__ unsigned int g_count = 0;

// XOR swizzle on float4 index: makes stride-2 idx4 accesses conflict-free.
__device__ __forceinline__ int swz(int i4) { return i4 ^ ((i4 >> 3) & 7); }

__global__ __launch_bounds__(TPB) void ssim_main(const float* __restrict__ pred,
                                                 const float* __restrict__ targ,
                                                 float* __restrict__ out)
{
    const int band = blockIdx.x;
    const int img  = blockIdx.y;
    const int r0   = band * RPB;
    int rend = r0 + RPB - 1;
    if (rend > OHH - 1) rend = OHH - 1;

    const int t = threadIdx.x;          // 0..63
    const int c = t << 3;               // 8 cols per thread, c in [0,504]

    // Double-buffered staging of the 5 vertical sums, swizzled float4 layout.
    __shared__ float4 sv[2][5][136];
    __shared__ float  wsum[2];
    __shared__ int    is_last;
    __shared__ double dred[TPB];

    // Zero the pad region (phys float4 idx 128..135) of every q/buffer so
    // out-of-range halo reads are benign (never NaN).
    {
        const float4 z4 = make_float4(0.f, 0.f, 0.f, 0.f);
        for (int i = t; i < 80; i += TPB) {
            int b = i / 40, rem = i % 40;
            sv[b][rem / 8][128 + (rem & 7)] = z4;
        }
    }

    // Loop-invariant swizzled smem indices.
    const int i_s0 = swz(2 * t);
    const int i_s1 = swz(2 * t + 1);
    const int i_l0 = swz(2 * t + 2);
    const int i_l1 = swz(2 * t + 3);
    const int i_l2 = swz(2 * t + 4);

    const float* pb = pred + img * (HH * WW);
    const float* qb = targ + img * (HH * WW);

    float s[5][8];   // vertical sliding sums: x, y, xx, yy, xy
#pragma unroll
    for (int q = 0; q < 5; ++q)
#pragma unroll
        for (int j = 0; j < 8; ++j) s[q][j] = 0.f;

    // Warm-up: rows r0 .. r0+9.
    for (int rr = r0; rr < r0 + WIN - 1; ++rr) {
        const float4 p0 = *(const float4*)(pb + rr * WW + c);
        const float4 p1 = *(const float4*)(pb + rr * WW + c + 4);
        const float4 q0 = *(const float4*)(qb + rr * WW + c);
        const float4 q1 = *(const float4*)(qb + rr * WW + c + 4);
        const float pj[8] = {p0.x,p0.y,p0.z,p0.w,p1.x,p1.y,p1.z,p1.w};
        const float qj[8] = {q0.x,q0.y,q0.z,q0.w,q1.x,q1.y,q1.z,q1.w};
#pragma unroll
        for (int j = 0; j < 8; ++j) {
            s[0][j] += pj[j];
            s[1][j] += qj[j];
            s[2][j] = fmaf(pj[j], pj[j], s[2][j]);
            s[3][j] = fmaf(qj[j], qj[j], s[3][j]);
            s[4][j] = fmaf(pj[j], qj[j], s[4][j]);
        }
    }

    const float inv_np = 1.0f / 121.0f;
    const float k120   = 1.0f / 120.0f;     // cov_norm / NP
    const float cn     = 121.0f / 120.0f;   // cov_norm
    const float C1     = 1.0e-4f;
    const float C2     = 9.0e-4f;

    float acc = 0.0f;

    for (int orow = r0; orow <= rend; ++orow) {
        const int par = orow & 1;

        // New bottom row (orow+10) and old top row (orow).
        const float4 pn0 = *(const float4*)(pb + (orow + WIN - 1) * WW + c);
        const float4 pn1 = *(const float4*)(pb + (orow + WIN - 1) * WW + c + 4);
        const float4 qn0 = *(const float4*)(qb + (orow + WIN - 1) * WW + c);
        const float4 qn1 = *(const float4*)(qb + (orow + WIN - 1) * WW + c + 4);
        const float4 po0 = *(const float4*)(pb + orow * WW + c);
        const float4 po1 = *(const float4*)(pb + orow * WW + c + 4);
        const float4 qo0 = *(const float4*)(qb + orow * WW + c);
        const float4 qo1 = *(const float4*)(qb + orow * WW + c + 4);

        {   // add new row -> sums cover rows orow..orow+10
            const float pj[8] = {pn0.x,pn0.y,pn0.z,pn0.w,pn1.x,pn1.y,pn1.z,pn1.w};
            const float qj[8] = {qn0.x,qn0.y,qn0.z,qn0.w,qn1.x,qn1.y,qn1.z,qn1.w};
#pragma unroll
            for (int j = 0; j < 8; ++j) {
                s[0][j] += pj[j];
                s[1][j] += qj[j];
                s[2][j] = fmaf(pj[j], pj[j], s[2][j]);
                s[3][j] = fmaf(qj[j], qj[j], s[3][j]);
                s[4][j] = fmaf(pj[j], qj[j], s[4][j]);
            }
        }

        // Stage vertical sums (swizzled).
#pragma unroll
        for (int q = 0; q < 5; ++q) {
            sv[par][q][i_s0] = make_float4(s[q][0], s[q][1], s[q][2], s[q][3]);
            sv[par][q][i_s1] = make_float4(s[q][4], s[q][5], s[q][6], s[q][7]);
        }
        __syncthreads();

        // Horizontal 11-window sliding sums; own 8 values come from registers,
        // halo (cols c+8..c+19) from smem.
        float w[5][8];
#pragma unroll
        for (int q = 0; q < 5; ++q) {
            const float4 n0 = sv[par][q][i_l0];
            const float4 n1 = sv[par][q][i_l1];
            const float4 n2 = sv[par][q][i_l2];
            const float nb[10] = {n0.x,n0.y,n0.z,n0.w,n1.x,n1.y,n1.z,n1.w,n2.x,n2.y};
            float w0 = s[q][0] + s[q][1] + s[q][2] + s[q][3]
                     + s[q][4] + s[q][5] + s[q][6] + s[q][7]
                     + nb[0] + nb[1] + nb[2];              // cols c..c+10
            w[q][0] = w0;
#pragma unroll
            for (int j = 1; j < 8; ++j) {
                w0 = w0 - s[q][j - 1] + nb[j + 2];          // cols c+j..c+j+10
                w[q][j] = w0;
            }
        }

        // SSIM per output pixel.
#pragma unroll
        for (int j = 0; j < 8; ++j) {
            const float ux  = w[0][j] * inv_np;
            const float uy  = w[1][j] * inv_np;
            const float ux2 = ux * ux;
            const float uy2 = uy * uy;
            const float uxy = ux * uy;
            const float vx  = fmaf(w[2][j], k120, -cn * ux2);
            const float vy  = fmaf(w[3][j], k120, -cn * uy2);
            const float vxy = fmaf(w[4][j], k120, -cn * uxy);
            const float A1  = fmaf(2.0f, uxy, C1);
            const float A2  = fmaf(2.0f, vxy, C2);
            const float B1  = ux2 + uy2 + C1;
            const float B2  = vx + vy + C2;
            const float S   = __fdividef(A1 * A2, B1 * B2);
            if (c + j < OWW) acc += S;
        }

        {   // subtract old top row -> sums cover orow+1..orow+10
            const float pj[8] = {po0.x,po0.y,po0.z,po0.w,po1.x,po1.y,po1.z,po1.w};
            const float qj[8] = {qo0.x,qo0.y,qo0.z,qo0.w,qo1.x,qo1.y,qo1.z,qo1.w};
#pragma unroll
            for (int j = 0; j < 8; ++j) {
                s[0][j] -= pj[j];
                s[1][j] -= qj[j];
                s[2][j] = fmaf(-pj[j], pj[j], s[2][j]);
                s[3][j] = fmaf(-qj[j], qj[j], s[3][j]);
                s[4][j] = fmaf(-pj[j], qj[j], s[4][j]);
            }
        }
    }

    // Block reduction (2 warps).
    float v = acc;
#pragma unroll
    for (int off = 16; off; off >>= 1)
        v += __shfl_xor_sync(0xffffffffu, v, off);
    const int lane = t & 31, wid = t >> 5;
    if (lane == 0) wsum[wid] = v;
    __syncthreads();

    if (t == 0) {
        g_partial[img * NBANDS + band] = wsum[0] + wsum[1];
        __threadfence();
        const unsigned int tick = atomicAdd(&g_count, 1u);
        is_last = (tick == NBLK - 1);
    }
    __syncthreads();

    // Last block performs the deterministic final reduction.
    if (is_last) {
        __threadfence();
        double sd = 0.0;
        for (int i = t; i < NBLK; i += TPB)   // fixed slots, fixed order
            sd += (double)g_partial[i];
        dred[t] = sd;
        __syncthreads();
#pragma unroll
        for (int st = TPB / 2; st > 0; st >>= 1) {
            if (t < st) dred[t] += dred[t + st];
            __syncthreads();
        }
        if (t == 0) {
            out[0] = (float)(1.0 - dred[0] / ((double)BATCH * OHH * OWW));
            g_count = 0;   // reset for next graph replay
        }
    }
}

extern "C" void kernel_launch(void* const* d_in, const int* in_sizes, int n_in,
                              void* d_out, int out_size)
{
    const float* pred = (const float*)d_in[0];
    const float* targ = (const float*)d_in[1];
    float* out = (float*)d_out;

    ssim_main<<<dim3(NBANDS, BATCH), TPB>>>(pred, targ, out);
}

// round 5
// speedup vs baseline: 1.1484x; 1.1484x over previous
#include <cuda_runtime.h>

// Fused SSIM loss. pred/target: [32,1,512,512] f32, WIN=11 VALID -> 502x502.
// out[0] = 1 - mean(S).
//
// R4: TPB=128, 4 cols/thread, forced 8 blocks/SM (<=64 regs) to raise the
// occupancy CAP (R3 showed occupancy was reg/smem-capped, not grid-capped).
// Double-buffered consecutive-index float4 staging (conflict-free, no swizzle),
// 1 barrier/row, deterministic last-block final reduction.

#define BATCH   32
#define HH      512
#define WW      512
#define WIN     11
#define OHH     502
#define OWW     502
#define NBANDS  36
#define RPB     14
#define TPB     128
#define NBLK    (BATCH * NBANDS)   // 1152

__device__ float        g_partial[NBLK];
__device__ unsigned int g_count = 0;

__global__ __launch_bounds__(TPB, 8) void ssim_main(const float* __restrict__ pred,
                                                    const float* __restrict__ targ,
                                                    float* __restrict__ out)
{
    const int band = blockIdx.x;
    const int img  = blockIdx.y;
    const int r0   = band * RPB;
    int rend = r0 + RPB - 1;
    if (rend > OHH - 1) rend = OHH - 1;

    const int t = threadIdx.x;          // 0..127
    const int c = t << 2;               // 4 cols per thread, c in [0,508]

    // Double-buffered staging of 5 vertical-sum rows; float4 index = thread id.
    // Loads at t+1..t+3 are consecutive -> conflict-free. Pad 128..131 zeroed.
    __shared__ float4 sv[2][5][132];
    __shared__ float  wsum[4];
    __shared__ int    is_last;
    __shared__ double dred[TPB];

    {
        const float4 z4 = make_float4(0.f, 0.f, 0.f, 0.f);
        if (t < 40) {                   // 2 buf * 5 q * 4 pad entries
            int b = t / 20, rem = t % 20;
            sv[b][rem / 4][128 + (rem & 3)] = z4;
        }
    }

    const float* pb = pred + img * (HH * WW);
    const float* qb = targ + img * (HH * WW);

    float s[5][4];   // vertical sliding sums: x, y, xx, yy, xy
#pragma unroll
    for (int q = 0; q < 5; ++q)
#pragma unroll
        for (int j = 0; j < 4; ++j) s[q][j] = 0.f;

    // Warm-up: rows r0 .. r0+9.
    for (int rr = r0; rr < r0 + WIN - 1; ++rr) {
        const float4 p4 = *(const float4*)(pb + rr * WW + c);
        const float4 q4 = *(const float4*)(qb + rr * WW + c);
        const float pj[4] = {p4.x, p4.y, p4.z, p4.w};
        const float qj[4] = {q4.x, q4.y, q4.z, q4.w};
#pragma unroll
        for (int j = 0; j < 4; ++j) {
            s[0][j] += pj[j];
            s[1][j] += qj[j];
            s[2][j] = fmaf(pj[j], pj[j], s[2][j]);
            s[3][j] = fmaf(qj[j], qj[j], s[3][j]);
            s[4][j] = fmaf(pj[j], qj[j], s[4][j]);
        }
    }

    const float inv_np = 1.0f / 121.0f;
    const float k120   = 1.0f / 120.0f;     // cov_norm / NP
    const float cn     = 121.0f / 120.0f;   // cov_norm
    const float C1     = 1.0e-4f;
    const float C2     = 9.0e-4f;

    float acc = 0.0f;

    for (int orow = r0; orow <= rend; ++orow) {
        const int par = orow & 1;

        // New bottom row (orow+10) and old top row (orow).
        const float4 pn = *(const float4*)(pb + (orow + WIN - 1) * WW + c);
        const float4 qn = *(const float4*)(qb + (orow + WIN - 1) * WW + c);
        const float4 po = *(const float4*)(pb + orow * WW + c);
        const float4 qo = *(const float4*)(qb + orow * WW + c);

        {   // add new row -> sums cover rows orow..orow+10
            const float pj[4] = {pn.x, pn.y, pn.z, pn.w};
            const float qj[4] = {qn.x, qn.y, qn.z, qn.w};
#pragma unroll
            for (int j = 0; j < 4; ++j) {
                s[0][j] += pj[j];
                s[1][j] += qj[j];
                s[2][j] = fmaf(pj[j], pj[j], s[2][j]);
                s[3][j] = fmaf(qj[j], qj[j], s[3][j]);
                s[4][j] = fmaf(qj[j], pj[j], s[4][j]);
            }
        }

        // Stage vertical sums.
#pragma unroll
        for (int q = 0; q < 5; ++q)
            sv[par][q][t] = make_float4(s[q][0], s[q][1], s[q][2], s[q][3]);
        __syncthreads();

        // Horizontal 11-window sliding sums; own 4 values from registers,
        // halo (cols c+4..c+13) from smem.
        float w[5][4];
#pragma unroll
        for (int q = 0; q < 5; ++q) {
            const float4 n0 = sv[par][q][t + 1];
            const float4 n1 = sv[par][q][t + 2];
            const float4 n2 = sv[par][q][t + 3];
            float w0 = s[q][0] + s[q][1] + s[q][2] + s[q][3]
                     + n0.x + n0.y + n0.z + n0.w
                     + n1.x + n1.y + n1.z;                  // cols c..c+10
            float w1 = w0 - s[q][0] + n1.w;                 // c+1..c+11
            float w2 = w1 - s[q][1] + n2.x;                 // c+2..c+12
            float w3 = w2 - s[q][2] + n2.y;                 // c+3..c+13
            w[q][0] = w0; w[q][1] = w1; w[q][2] = w2; w[q][3] = w3;
        }

        // SSIM per output pixel.
#pragma unroll
        for (int j = 0; j < 4; ++j) {
            const float ux  = w[0][j] * inv_np;
            const float uy  = w[1][j] * inv_np;
            const float ux2 = ux * ux;
            const float uy2 = uy * uy;
            const float uxy = ux * uy;
            const float vx  = fmaf(w[2][j], k120, -cn * ux2);
            const float vy  = fmaf(w[3][j], k120, -cn * uy2);
            const float vxy = fmaf(w[4][j], k120, -cn * uxy);
            const float A1  = fmaf(2.0f, uxy, C1);
            const float A2  = fmaf(2.0f, vxy, C2);
            const float B1  = ux2 + uy2 + C1;
            const float B2  = vx + vy + C2;
            const float S   = __fdividef(A1 * A2, B1 * B2);
            if (c + j < OWW) acc += S;
        }

        {   // subtract old top row -> sums cover orow+1..orow+10
            const float pj[4] = {po.x, po.y, po.z, po.w};
            const float qj[4] = {qo.x, qo.y, qo.z, qo.w};
#pragma unroll
            for (int j = 0; j < 4; ++j) {
                s[0][j] -= pj[j];
                s[1][j] -= qj[j];
                s[2][j] = fmaf(-pj[j], pj[j], s[2][j]);
                s[3][j] = fmaf(-qj[j], qj[j], s[3][j]);
                s[4][j] = fmaf(-qj[j], pj[j], s[4][j]);
            }
        }
    }

    // Block reduction (4 warps).
    float v = acc;
#pragma unroll
    for (int off = 16; off; off >>= 1)
        v += __shfl_xor_sync(0xffffffffu, v, off);
    const int lane = t & 31, wid = t >> 5;
    if (lane == 0) wsum[wid] = v;
    __syncthreads();

    if (t == 0) {
        g_partial[img * NBANDS + band] = wsum[0] + wsum[1] + wsum[2] + wsum[3];
        __threadfence();
        const unsigned int tick = atomicAdd(&g_count, 1u);
        is_last = (tick == NBLK - 1);
    }
    __syncthreads();

    // Last block performs the deterministic final reduction.
    if (is_last) {
        __threadfence();
        double sd = 0.0;
        for (int i = t; i < NBLK; i += TPB)   // fixed slots, fixed order
            sd += (double)g_partial[i];
        dred[t] = sd;
        __syncthreads();
#pragma unroll
        for (int st = TPB / 2; st > 0; st >>= 1) {
            if (t < st) dred[t] += dred[t + st];
            __syncthreads();
        }
        if (t == 0) {
            out[0] = (float)(1.0 - dred[0] / ((double)BATCH * OHH * OWW));
            g_count = 0;   // reset for next graph replay
        }
    }
}

extern "C" void kernel_launch(void* const* d_in, const int* in_sizes, int n_in,
                              void* d_out, int out_size)
{
    const float* pred = (const float*)d_in[0];
    const float* targ = (const float*)d_in[1];
    float* out = (float*)d_out;

    ssim_main<<<dim3(NBANDS, BATCH), TPB>>>(pred, targ, out);
}

// round 6
// speedup vs baseline: 1.3040x; 1.1355x over previous
#include <cuda_runtime.h>

// Fused SSIM loss. pred/target: [32,1,512,512] f32, WIN=11 VALID -> 502x502.
// out[0] = 1 - mean(S).
//
// R5: software-pipeline the new-bottom-row global loads one iteration ahead
// (R4 showed the per-row L2 latency was exposed in lockstep at the barrier).
// Horizontal+SSIM streamed per column to cut live registers. (128,7) bounds,
// one full wave of 1024 blocks at 7 blocks/SM.

#define BATCH   32
#define HH      512
#define WW      512
#define WIN     11
#define OHH     502
#define OWW     502
#define NBANDS  32
#define RPB     16
#define TPB     128
#define NBLK    (BATCH * NBANDS)   // 1024

__device__ float        g_partial[NBLK];
__device__ unsigned int g_count = 0;

__global__ __launch_bounds__(TPB, 7) void ssim_main(const float* __restrict__ pred,
                                                    const float* __restrict__ targ,
                                                    float* __restrict__ out)
{
    const int band = blockIdx.x;
    const int img  = blockIdx.y;
    const int r0   = band * RPB;
    int rend = r0 + RPB - 1;
    if (rend > OHH - 1) rend = OHH - 1;

    const int t = threadIdx.x;          // 0..127
    const int c = t << 2;               // 4 cols per thread, c in [0,508]

    // Double-buffered staging of 5 vertical-sum rows; float4 index = thread id.
    // Loads at t+1..t+3 are consecutive -> conflict-free. Pad 128..131 zeroed.
    __shared__ float4 sv[2][5][132];
    __shared__ float  wsum[4];
    __shared__ int    is_last;
    __shared__ double dred[TPB];

    {
        const float4 z4 = make_float4(0.f, 0.f, 0.f, 0.f);
        if (t < 40) {                   // 2 buf * 5 q * 4 pad entries
            int b = t / 20, rem = t % 20;
            sv[b][rem / 4][128 + (rem & 3)] = z4;
        }
    }

    const float* pb = pred + img * (HH * WW);
    const float* qb = targ + img * (HH * WW);

    float s[5][4];   // vertical sliding sums: x, y, xx, yy, xy
#pragma unroll
    for (int q = 0; q < 5; ++q)
#pragma unroll
        for (int j = 0; j < 4; ++j) s[q][j] = 0.f;

    // Warm-up: rows r0 .. r0+9.
    for (int rr = r0; rr < r0 + WIN - 1; ++rr) {
        const float4 p4 = *(const float4*)(pb + rr * WW + c);
        const float4 q4 = *(const float4*)(qb + rr * WW + c);
        const float pj[4] = {p4.x, p4.y, p4.z, p4.w};
        const float qj[4] = {q4.x, q4.y, q4.z, q4.w};
#pragma unroll
        for (int j = 0; j < 4; ++j) {
            s[0][j] += pj[j];
            s[1][j] += qj[j];
            s[2][j] = fmaf(pj[j], pj[j], s[2][j]);
            s[3][j] = fmaf(qj[j], qj[j], s[3][j]);
            s[4][j] = fmaf(pj[j], qj[j], s[4][j]);
        }
    }

    const float inv_np = 1.0f / 121.0f;
    const float k120   = 1.0f / 120.0f;     // cov_norm / NP
    const float cn     = 121.0f / 120.0f;   // cov_norm
    const float C1     = 1.0e-4f;
    const float C2     = 9.0e-4f;

    float acc = 0.0f;

    // Pipeline prologue: preload bottom row for the first iteration.
    float4 pn = *(const float4*)(pb + (r0 + WIN - 1) * WW + c);
    float4 qn = *(const float4*)(qb + (r0 + WIN - 1) * WW + c);

    for (int orow = r0; orow <= rend; ++orow) {
        const int par = orow & 1;

        // Old top row (consumed at the end of this iteration -> latency hidden).
        const float4 po = *(const float4*)(pb + orow * WW + c);
        const float4 qo = *(const float4*)(qb + orow * WW + c);

        {   // add prefetched new row -> sums cover rows orow..orow+10
            const float pj[4] = {pn.x, pn.y, pn.z, pn.w};
            const float qj[4] = {qn.x, qn.y, qn.z, qn.w};
#pragma unroll
            for (int j = 0; j < 4; ++j) {
                s[0][j] += pj[j];
                s[1][j] += qj[j];
                s[2][j] = fmaf(pj[j], pj[j], s[2][j]);
                s[3][j] = fmaf(qj[j], qj[j], s[3][j]);
                s[4][j] = fmaf(qj[j], pj[j], s[4][j]);
            }
        }

        // Stage vertical sums.
#pragma unroll
        for (int q = 0; q < 5; ++q)
            sv[par][q][t] = make_float4(s[q][0], s[q][1], s[q][2], s[q][3]);

        // Prefetch next iteration's bottom row NOW (clamped; covered by
        // barrier + horizontal + SSIM below).
        {
            int rnext = orow + WIN;                 // (orow+1) + 10
            if (rnext > HH - 1) rnext = HH - 1;
            pn = *(const float4*)(pb + rnext * WW + c);
            qn = *(const float4*)(qb + rnext * WW + c);
        }

        __syncthreads();

        // Horizontal 11-window sums, streamed: compute w[q] for col c, do
        // SSIM, slide. Slide-in scalars cached; halo from smem.
        float w[5];
        float si1[5], si2[5], si3[5];
#pragma unroll
        for (int q = 0; q < 5; ++q) {
            const float4 n0 = sv[par][q][t + 1];
            const float4 n1 = sv[par][q][t + 2];
            const float4 n2 = sv[par][q][t + 3];
            w[q] = s[q][0] + s[q][1] + s[q][2] + s[q][3]
                 + n0.x + n0.y + n0.z + n0.w
                 + n1.x + n1.y + n1.z;              // cols c..c+10
            si1[q] = n1.w; si2[q] = n2.x; si3[q] = n2.y;
        }

#pragma unroll
        for (int j = 0; j < 4; ++j) {
            if (j) {
                const float* si = (j == 1) ? si1 : (j == 2) ? si2 : si3;
#pragma unroll
                for (int q = 0; q < 5; ++q)
                    w[q] = w[q] - s[q][j - 1] + si[q];
            }
            const float ux  = w[0] * inv_np;
            const float uy  = w[1] * inv_np;
            const float ux2 = ux * ux;
            const float uy2 = uy * uy;
            const float uxy = ux * uy;
            const float vx  = fmaf(w[2], k120, -cn * ux2);
            const float vy  = fmaf(w[3], k120, -cn * uy2);
            const float vxy = fmaf(w[4], k120, -cn * uxy);
            const float A1  = fmaf(2.0f, uxy, C1);
            const float A2  = fmaf(2.0f, vxy, C2);
            const float B1  = ux2 + uy2 + C1;
            const float B2  = vx + vy + C2;
            const float S   = __fdividef(A1 * A2, B1 * B2);
            if (c + j < OWW) acc += S;
        }

        {   // subtract old top row -> sums cover orow+1..orow+10
            const float pj[4] = {po.x, po.y, po.z, po.w};
            const float qj[4] = {qo.x, qo.y, qo.z, qo.w};
#pragma unroll
            for (int j = 0; j < 4; ++j) {
                s[0][j] -= pj[j];
                s[1][j] -= qj[j];
                s[2][j] = fmaf(-pj[j], pj[j], s[2][j]);
                s[3][j] = fmaf(-qj[j], qj[j], s[3][j]);
                s[4][j] = fmaf(-qj[j], pj[j], s[4][j]);
            }
        }
    }

    // Block reduction (4 warps).
    float v = acc;
#pragma unroll
    for (int off = 16; off; off >>= 1)
        v += __shfl_xor_sync(0xffffffffu, v, off);
    const int lane = t & 31, wid = t >> 5;
    if (lane == 0) wsum[wid] = v;
    __syncthreads();

    if (t == 0) {
        g_partial[img * NBANDS + band] = wsum[0] + wsum[1] + wsum[2] + wsum[3];
        __threadfence();
        const unsigned int tick = atomicAdd(&g_count, 1u);
        is_last = (tick == NBLK - 1);
    }
    __syncthreads();

    // Last block performs the deterministic final reduction.
    if (is_last) {
        __threadfence();
        double sd = 0.0;
        for (int i = t; i < NBLK; i += TPB)   // fixed slots, fixed order
            sd += (double)g_partial[i];
        dred[t] = sd;
        __syncthreads();
#pragma unroll
        for (int st = TPB / 2; st > 0; st >>= 1) {
            if (t < st) dred[t] += dred[t + st];
            __syncthreads();
        }
        if (t == 0) {
            out[0] = (float)(1.0 - dred[0] / ((double)BATCH * OHH * OWW));
            g_count = 0;   // reset for next graph replay
        }
    }
}

extern "C" void kernel_launch(void* const* d_in, const int* in_sizes, int n_in,
                              void* d_out, int out_size)
{
    const float* pred = (const float*)d_in[0];
    const float* targ = (const float*)d_in[1];
    float* out = (float*)d_out;

    ssim_main<<<dim3(NBANDS, BATCH), TPB>>>(pred, targ, out);
}